// round 3
// baseline (speedup 1.0000x reference)
#include <cuda_runtime.h>

#define EPSF     1e-8f
#define PSD_EPSF 1e-5f

constexpr int Bn = 8, Cn = 8, Fn = 257, Tn = 1500;
constexpr int T2  = Tn / 2;          // 750 float2 chunks per row
constexpr int FT2 = Fn * T2;         // float2 stride between channels
constexpr int BF  = Bn * Fn;         // 2056
constexpr int BFT = Bn * Fn * Tn;    // 3,084,000

// Scratch (no allocations allowed): reciprocal of per-(b,t) mask max, and conj(weights).
__device__ float2 g_recip_s[Bn * T2];
__device__ float2 g_recip_n[Bn * T2];
__device__ float2 g_wconj[BF * Cn];

// ---------------------------------------------------------------------------
// Kernel A: max_|mask| over F per (b, t); store 1/(max+eps). Coalesced over t.
// ---------------------------------------------------------------------------
__global__ void mask_max_kernel(const float* __restrict__ sm,
                                const float* __restrict__ nm) {
    int b   = blockIdx.y;
    int idx = blockIdx.x * blockDim.x + threadIdx.x;
    if (idx >= T2) return;
    const float2* s = (const float2*)sm + (size_t)b * Fn * T2 + idx;
    const float2* n = (const float2*)nm + (size_t)b * Fn * T2 + idx;
    float2 ms = make_float2(0.f, 0.f), mn = make_float2(0.f, 0.f);
#pragma unroll 4
    for (int f = 0; f < Fn; f++) {
        float2 v = s[(size_t)f * T2];
        ms.x = fmaxf(ms.x, fabsf(v.x));
        ms.y = fmaxf(ms.y, fabsf(v.y));
        float2 w = n[(size_t)f * T2];
        mn.x = fmaxf(mn.x, fabsf(w.x));
        mn.y = fmaxf(mn.y, fabsf(w.y));
    }
    g_recip_s[b * T2 + idx] = make_float2(1.f / (ms.x + EPSF), 1.f / (ms.y + EPSF));
    g_recip_n[b * T2 + idx] = make_float2(1.f / (mn.x + EPSF), 1.f / (mn.y + EPSF));
}

// ---------------------------------------------------------------------------
// Kernel B: per (b,f) block. Accumulate Hermitian speech/noise PSD over T,
// reduce across the block, then invert noise PSD (Gauss-Jordan in shared)
// and compute conj(MVDR weights) directly.
// ---------------------------------------------------------------------------
__global__ __launch_bounds__(128, 2)
void psd_weight_kernel(const float* __restrict__ smk,
                       const float* __restrict__ nmk,
                       const float* __restrict__ cr,
                       const float* __restrict__ ci) {
    int bf = blockIdx.x;
    int b  = bf / Fn, f = bf % Fn;

    const float2* smr = (const float2*)smk + (size_t)bf * T2;
    const float2* nmr = (const float2*)nmk + (size_t)bf * T2;
    const float2* rs  = g_recip_s + b * T2;
    const float2* rn  = g_recip_n + b * T2;
    const float2* xr0 = (const float2*)cr + (size_t)b * Cn * FT2 + (size_t)f * T2;
    const float2* xi0 = (const float2*)ci + (size_t)b * Cn * FT2 + (size_t)f * T2;

    // Packed Hermitian upper triangle: p(c,d) = 8c - c(c-1)/2 + (d-c), c<=d.
    float asr[36], asi[36], anr[36], ani[36];
#pragma unroll
    for (int p = 0; p < 36; p++) { asr[p] = 0.f; asi[p] = 0.f; anr[p] = 0.f; ani[p] = 0.f; }
    float ds = 0.f, dn = 0.f;

    for (int t = threadIdx.x; t < T2; t += 128) {
        float2 m1 = smr[t], r1 = rs[t];
        float2 m2 = nmr[t], r2 = rn[t];
        float msv[2] = { m1.x * r1.x, m1.y * r1.y };
        float mnv[2] = { m2.x * r2.x, m2.y * r2.y };
        float2 XR[8], XI[8];
#pragma unroll
        for (int c = 0; c < 8; c++) {
            XR[c] = xr0[(size_t)c * FT2 + t];
            XI[c] = xi0[(size_t)c * FT2 + t];
        }
#pragma unroll
        for (int j = 0; j < 2; j++) {
            float ms = msv[j], mn = mnv[j];
            ds += ms; dn += mn;
            float xr[8], xi[8];
#pragma unroll
            for (int c = 0; c < 8; c++) {
                xr[c] = j ? XR[c].y : XR[c].x;
                xi[c] = j ? XI[c].y : XI[c].x;
            }
#pragma unroll
            for (int c = 0; c < 8; c++) {
                float ar = xr[c], ai = xi[c];
#pragma unroll
                for (int d = c; d < 8; d++) {
                    int   p  = c * 8 - (c * (c - 1)) / 2 + (d - c);
                    float br = xr[d], bi = xi[d];
                    float ore = ar * br + ai * bi;     // Re{x_c conj(x_d)}
                    float oim = ai * br - ar * bi;     // Im{x_c conj(x_d)}
                    asr[p] += ms * ore;  asi[p] += ms * oim;
                    anr[p] += mn * ore;  ani[p] += mn * oim;
                }
            }
        }
    }

    // Warp-level reduction of the 146 accumulators.
#pragma unroll
    for (int o = 16; o > 0; o >>= 1) {
        ds += __shfl_xor_sync(~0u, ds, o);
        dn += __shfl_xor_sync(~0u, dn, o);
#pragma unroll
        for (int p = 0; p < 36; p++) {
            asr[p] += __shfl_xor_sync(~0u, asr[p], o);
            asi[p] += __shfl_xor_sync(~0u, asi[p], o);
            anr[p] += __shfl_xor_sync(~0u, anr[p], o);
            ani[p] += __shfl_xor_sync(~0u, ani[p], o);
        }
    }

    __shared__ float red[4][146];
    int warp = threadIdx.x >> 5, lane = threadIdx.x & 31;
    if (lane == 0) {
        red[warp][0] = ds;
        red[warp][1] = dn;
#pragma unroll
        for (int p = 0; p < 36; p++) {
            red[warp][2 + p]   = asr[p];
            red[warp][38 + p]  = asi[p];
            red[warp][74 + p]  = anr[p];
            red[warp][110 + p] = ani[p];
        }
    }
    __syncthreads();

    __shared__ float fin[146];
    for (int i = threadIdx.x; i < 146; i += 128)
        fin[i] = red[0][i] + red[1][i] + red[2][i] + red[3][i];
    __syncthreads();

    // Build full 8x8 matrices in shared: Sp (speech PSD) and Aug = [Noise | I].
    __shared__ float2 Aug[8][16];
    __shared__ float2 Sp[8][8];
    if (threadIdx.x < 64) {
        int c = threadIdx.x >> 3, d = threadIdx.x & 7;
        float dens = fmaxf(fin[0], PSD_EPSF);
        float denn = fmaxf(fin[1], PSD_EPSF);
        int lo = min(c, d), hi = max(c, d);
        int p  = lo * 8 - (lo * (lo - 1)) / 2 + (hi - lo);
        float sgn = (c <= d) ? 1.f : -1.f;   // conj for lower triangle
        float sre = fin[2 + p] / dens;
        float sim = sgn * fin[38 + p] / dens + (PSD_EPSF + EPSF);   // +i*PSD_EPS +i*eps
        float nre = fin[74 + p] / denn;
        float nim = sgn * fin[110 + p] / denn + (PSD_EPSF + EPSF);
        if (c == d) nre += EPSF;             // + eye*eps before inversion
        Sp[c][d]     = make_float2(sre, sim);
        Aug[c][d]    = make_float2(nre, nim);
        Aug[c][d + 8] = make_float2((c == d) ? 1.f : 0.f, 0.f);
    }
    __syncthreads();

    // Gauss-Jordan inversion by warp 0 (rows 0..7), then weights by lanes 0..7.
    if (threadIdx.x < 32) {
        int i = threadIdx.x;
        for (int k = 0; k < 8; k++) {
            if (i == k) {
                float2 piv = Aug[k][k];
                float invm = 1.f / (piv.x * piv.x + piv.y * piv.y);
                float pr = piv.x * invm, pi = -piv.y * invm;
#pragma unroll
                for (int j = 0; j < 16; j++) {
                    float2 v = Aug[k][j];
                    Aug[k][j] = make_float2(v.x * pr - v.y * pi, v.x * pi + v.y * pr);
                }
            }
            __syncwarp();
            if (i < 8 && i != k) {
                float2 fc = Aug[i][k];
#pragma unroll
                for (int j = 0; j < 16; j++) {
                    float2 v = Aug[k][j];
                    float2 w = Aug[i][j];
                    Aug[i][j] = make_float2(w.x - (fc.x * v.x - fc.y * v.y),
                                            w.y - (fc.x * v.y + fc.y * v.x));
                }
            }
            __syncwarp();
        }
        if (i < 8) {
            float2 inv[8];
#pragma unroll
            for (int d = 0; d < 8; d++) {
                inv[d] = Aug[i][8 + d];
                inv[d].y += EPSF;            // noise_psd_inv + i*eps
            }
            float2 trp = make_float2(0.f, 0.f), u = make_float2(0.f, 0.f);
#pragma unroll
            for (int d = 0; d < 8; d++) {
                float2 s1 = Sp[d][i];        // trace contribution of row i
                trp.x += inv[d].x * s1.x - inv[d].y * s1.y;
                trp.y += inv[d].x * s1.y + inv[d].y * s1.x;
                float2 s0 = Sp[d][0];        // u = A[:,0]
                u.x += inv[d].x * s0.x - inv[d].y * s0.y;
                u.y += inv[d].x * s0.y + inv[d].y * s0.x;
            }
#pragma unroll
            for (int o = 4; o > 0; o >>= 1) {
                trp.x += __shfl_xor_sync(0xFF, trp.x, o);
                trp.y += __shfl_xor_sync(0xFF, trp.y, o);
            }
            trp.x += EPSF;                   // tr + eps
            float idn = 1.f / (trp.x * trp.x + trp.y * trp.y);
            float wr = (u.x * trp.x + u.y * trp.y) * idn;
            float wi = (u.y * trp.x - u.x * trp.y) * idn;
            g_wconj[bf * 8 + i] = make_float2(wr, -wi);  // store conj(w)
        }
    }
}

// ---------------------------------------------------------------------------
// Kernel C: out[b,f,t] = sum_c conj(w)_c * cm[b,c,f,t]; write real+imag planes.
// ---------------------------------------------------------------------------
__global__ void apply_kernel(const float* __restrict__ cr,
                             const float* __restrict__ ci,
                             float* __restrict__ out) {
    int bf = blockIdx.y;
    int b  = bf / Fn, f = bf % Fn;
    __shared__ float2 ws[8];
    if (threadIdx.x < 8) ws[threadIdx.x] = g_wconj[bf * 8 + threadIdx.x];
    __syncthreads();
    int idx = blockIdx.x * blockDim.x + threadIdx.x;
    if (idx >= T2) return;
    const float2* xr0 = (const float2*)cr + (size_t)b * Cn * FT2 + (size_t)f * T2 + idx;
    const float2* xi0 = (const float2*)ci + (size_t)b * Cn * FT2 + (size_t)f * T2 + idx;
    float2 ore = make_float2(0.f, 0.f), oim = make_float2(0.f, 0.f);
#pragma unroll
    for (int c = 0; c < 8; c++) {
        float2 xr = xr0[(size_t)c * FT2];
        float2 xi = xi0[(size_t)c * FT2];
        float2 w  = ws[c];   // (cr, ci) = conj(w)
        ore.x += w.x * xr.x - w.y * xi.x;
        ore.y += w.x * xr.y - w.y * xi.y;
        oim.x += w.x * xi.x + w.y * xr.x;
        oim.y += w.x * xi.y + w.y * xr.y;
    }
    float2* outr = (float2*)out + (size_t)bf * T2 + idx;
    float2* outi = (float2*)out + (size_t)(BFT / 2) + (size_t)bf * T2 + idx;
    *outr = ore;
    *outi = oim;
}

extern "C" void kernel_launch(void* const* d_in, const int* in_sizes, int n_in,
                              void* d_out, int out_size) {
    const float* sm = (const float*)d_in[0];
    const float* nm = (const float*)d_in[1];
    const float* cr = (const float*)d_in[2];
    const float* ci = (const float*)d_in[3];
    float* out = (float*)d_out;

    dim3 gA((T2 + 255) / 256, Bn);
    mask_max_kernel<<<gA, 256>>>(sm, nm);

    psd_weight_kernel<<<BF, 128>>>(sm, nm, cr, ci);

    dim3 gC((T2 + 255) / 256, BF);
    apply_kernel<<<gC, 256>>>(cr, ci, out);
}

// round 6
// speedup vs baseline: 1.0905x; 1.0905x over previous
#include <cuda_runtime.h>

#define EPSF     1e-8f
#define PSD_EPSF 1e-5f

typedef unsigned long long u64;

constexpr int Bn = 8, Cn = 8, Fn = 257, Tn = 1500;
constexpr int T2  = Tn / 2;          // 750 float2 per (b,f) row
constexpr int T4  = Tn / 4;          // 375 float4 per (b,f) row
constexpr int FT2 = Fn * T2;
constexpr int FT4 = Fn * T4;
constexpr int BF  = Bn * Fn;         // 2056
constexpr int NSLAB = 8;             // F split for the mask-max kernel
constexpr int FSLAB = 33;            // ceil(257/8)
constexpr int TC = 96;               // t-pairs per stage in PSD kernel
constexpr int NSTAGE = (T2 + TC - 1) / TC;   // 8 (last stage 78)

// Scratch (no allocations allowed)
__device__ float2 g_part_s[NSLAB * Bn * T2];
__device__ float2 g_part_n[NSLAB * Bn * T2];
__device__ float2 g_recip_s[Bn * T2];
__device__ float2 g_recip_n[Bn * T2];

// ---------------- packed f32x2 helpers ----------------
__device__ __forceinline__ u64 fma2(u64 a, u64 b, u64 c) {
    u64 d; asm("fma.rn.f32x2 %0,%1,%2,%3;" : "=l"(d) : "l"(a), "l"(b), "l"(c)); return d;
}
__device__ __forceinline__ u64 mul2(u64 a, u64 b) {
    u64 d; asm("mul.rn.f32x2 %0,%1,%2;" : "=l"(d) : "l"(a), "l"(b)); return d;
}
__device__ __forceinline__ u64 add2(u64 a, u64 b) {
    u64 d; asm("add.rn.f32x2 %0,%1,%2;" : "=l"(d) : "l"(a), "l"(b)); return d;
}
__device__ __forceinline__ u64 neg2(u64 a) { return a ^ 0x8000000080000000ull; }
__device__ __forceinline__ float2 upk(u64 v) {
    float2 f; f.x = __uint_as_float((unsigned)v); f.y = __uint_as_float((unsigned)(v >> 32)); return f;
}
__device__ __forceinline__ u64 lds64(const float2* p) {
    return *reinterpret_cast<const u64*>(p);
}

// ---------------------------------------------------------------------------
// A1: partial max over an F-slab per (b, t).  grid (6, Bn, NSLAB) x 128.
// ---------------------------------------------------------------------------
__global__ void mask_partial_kernel(const float* __restrict__ sm,
                                    const float* __restrict__ nm) {
    int b = blockIdx.y, z = blockIdx.z;
    int idx = blockIdx.x * 128 + threadIdx.x;
    if (idx >= T2) return;
    int f0 = z * FSLAB, f1 = min(Fn, f0 + FSLAB);
    const float2* s = (const float2*)sm + (size_t)b * FT2 + (size_t)f0 * T2 + idx;
    const float2* n = (const float2*)nm + (size_t)b * FT2 + (size_t)f0 * T2 + idx;
    float2 ms = make_float2(0.f, 0.f), mn = make_float2(0.f, 0.f);
#pragma unroll 4
    for (int f = f0; f < f1; f++) {
        float2 v = *s; s += T2;
        ms.x = fmaxf(ms.x, fabsf(v.x)); ms.y = fmaxf(ms.y, fabsf(v.y));
        float2 w = *n; n += T2;
        mn.x = fmaxf(mn.x, fabsf(w.x)); mn.y = fmaxf(mn.y, fabsf(w.y));
    }
    g_part_s[(z * Bn + b) * T2 + idx] = ms;
    g_part_n[(z * Bn + b) * T2 + idx] = mn;
}

// ---------------------------------------------------------------------------
// A2: reduce slabs, store 1/(max+eps).  grid (6, Bn) x 128.
// ---------------------------------------------------------------------------
__global__ void mask_recip_kernel() {
    int b = blockIdx.y;
    int idx = blockIdx.x * 128 + threadIdx.x;
    if (idx >= T2) return;
    float2 ms = make_float2(0.f, 0.f), mn = make_float2(0.f, 0.f);
#pragma unroll
    for (int z = 0; z < NSLAB; z++) {
        float2 v = g_part_s[(z * Bn + b) * T2 + idx];
        ms.x = fmaxf(ms.x, v.x); ms.y = fmaxf(ms.y, v.y);
        float2 w = g_part_n[(z * Bn + b) * T2 + idx];
        mn.x = fmaxf(mn.x, w.x); mn.y = fmaxf(mn.y, w.y);
    }
    g_recip_s[b * T2 + idx] = make_float2(1.f / (ms.x + EPSF), 1.f / (ms.y + EPSF));
    g_recip_n[b * T2 + idx] = make_float2(1.f / (mn.x + EPSF), 1.f / (mn.y + EPSF));
}

// ---------------------------------------------------------------------------
// Per-pair accumulation macro: literal channel indices keep register arrays.
// ---------------------------------------------------------------------------
#define PAIRB(K, C, D) { \
    u64 ar = vr[C], ai = vi[C], br = vr[D], bi = vi[D]; \
    u64 ore = fma2(ai, bi, mul2(ar, br)); \
    u64 oim = fma2(ai, br, neg2(mul2(ar, bi))); \
    aSr[K] = fma2(ms, ore, aSr[K]);  aSi[K] = fma2(ms, oim, aSi[K]); \
    aNr[K] = fma2(mn, ore, aNr[K]);  aNi[K] = fma2(mn, oim, aNi[K]); }

#define PAIRS_W0 PAIRB(0,0,0) PAIRB(1,0,4) PAIRB(2,1,1) PAIRB(3,1,5) PAIRB(4,2,3) PAIRB(5,2,7) PAIRB(6,3,6) PAIRB(7,4,6) PAIRB(8,5,7)
#define PAIRS_W1 PAIRB(0,0,1) PAIRB(1,0,5) PAIRB(2,1,2) PAIRB(3,1,6) PAIRB(4,2,4) PAIRB(5,3,3) PAIRB(6,3,7) PAIRB(7,4,7) PAIRB(8,6,6)
#define PAIRS_W2 PAIRB(0,0,2) PAIRB(1,0,6) PAIRB(2,1,3) PAIRB(3,1,7) PAIRB(4,2,5) PAIRB(5,3,4) PAIRB(6,4,4) PAIRB(7,5,5) PAIRB(8,6,7)
#define PAIRS_W3 PAIRB(0,0,3) PAIRB(1,0,7) PAIRB(2,1,4) PAIRB(3,2,2) PAIRB(4,2,6) PAIRB(5,3,5) PAIRB(6,4,5) PAIRB(7,5,6) PAIRB(8,7,7)

template<int W>
__device__ __forceinline__ void warp_rounds(
    int lane, int cnt,
    const float2 (&sXr)[8][TC], const float2 (&sXi)[8][TC],
    const float2* sMs, const float2* sMn,
    u64* aSr, u64* aSi, u64* aNr, u64* aNi, u64& dsum, u64& dnum)
{
    for (int j = lane; j < cnt; j += 32) {
        u64 vr[8], vi[8];
#pragma unroll
        for (int c = 0; c < 8; c++) { vr[c] = lds64(&sXr[c][j]); vi[c] = lds64(&sXi[c][j]); }
        u64 ms = lds64(&sMs[j]);
        u64 mn = lds64(&sMn[j]);
        if (W == 0) { dsum = add2(dsum, ms); dnum = add2(dnum, mn); }
        if (W == 0) { PAIRS_W0 }
        if (W == 1) { PAIRS_W1 }
        if (W == 2) { PAIRS_W2 }
        if (W == 3) { PAIRS_W3 }
    }
}

// ---------------------------------------------------------------------------
// Fused kernel: per (b,f) block — PSD accumulation (pair-split across warps,
// f32x2 packed), 8x8 complex inverse, MVDR weights, and weight application.
// ---------------------------------------------------------------------------
__global__ __launch_bounds__(128)
void psd_weight_apply_kernel(const float* __restrict__ smk,
                             const float* __restrict__ nmk,
                             const float* __restrict__ cr,
                             const float* __restrict__ ci,
                             float* __restrict__ out) {
    int bf = blockIdx.x;
    int b  = bf / Fn, f = bf % Fn;
    int tid = threadIdx.x, lane = tid & 31, w = tid >> 5;

    const float2* smr = (const float2*)smk + (size_t)bf * T2;
    const float2* nmr = (const float2*)nmk + (size_t)bf * T2;
    const float2* rs  = g_recip_s + b * T2;
    const float2* rn  = g_recip_n + b * T2;
    const float2* xr0 = (const float2*)cr + (size_t)b * Cn * FT2 + (size_t)f * T2;
    const float2* xi0 = (const float2*)ci + (size_t)b * Cn * FT2 + (size_t)f * T2;

    __shared__ float2 sXr[8][TC];
    __shared__ float2 sXi[8][TC];
    __shared__ float2 sMs[TC];
    __shared__ float2 sMn[TC];
    __shared__ float  fin[146];
    __shared__ float2 Aug[8][16];
    __shared__ float2 Sp[8][8];
    __shared__ float2 ws[8];

    u64 aSr[9], aSi[9], aNr[9], aNi[9];
#pragma unroll
    for (int k = 0; k < 9; k++) { aSr[k] = 0; aSi[k] = 0; aNr[k] = 0; aNi[k] = 0; }
    u64 dsum = 0, dnum = 0;

    for (int st = 0; st < NSTAGE; st++) {
        int t0  = st * TC;
        int cnt = min(TC, T2 - t0);
        __syncthreads();
        // stage cm tile into shared (one global read per element)
#pragma unroll
        for (int i = tid; i < 16 * TC; i += 128) {
            int s_ = i / TC, j = i - s_ * TC;
            if (j < cnt) {
                if (s_ < 8) sXr[s_][j] = xr0[(size_t)s_ * FT2 + t0 + j];
                else        sXi[s_ - 8][j] = xi0[(size_t)(s_ - 8) * FT2 + t0 + j];
            }
        }
        if (tid < TC && tid < cnt) {
            float2 m = smr[t0 + tid], r = rs[t0 + tid];
            sMs[tid] = make_float2(m.x * r.x, m.y * r.y);
            float2 m2 = nmr[t0 + tid], r2 = rn[t0 + tid];
            sMn[tid] = make_float2(m2.x * r2.x, m2.y * r2.y);
        }
        __syncthreads();
        if      (w == 0) warp_rounds<0>(lane, cnt, sXr, sXi, sMs, sMn, aSr, aSi, aNr, aNi, dsum, dnum);
        else if (w == 1) warp_rounds<1>(lane, cnt, sXr, sXi, sMs, sMn, aSr, aSi, aNr, aNi, dsum, dnum);
        else if (w == 2) warp_rounds<2>(lane, cnt, sXr, sXi, sMs, sMn, aSr, aSi, aNr, aNi, dsum, dnum);
        else             warp_rounds<3>(lane, cnt, sXr, sXi, sMs, sMn, aSr, aSi, aNr, aNi, dsum, dnum);
    }

    // warp-level reduction (u64 shuffles = 2x SHFL each)
#pragma unroll
    for (int o = 16; o > 0; o >>= 1) {
#pragma unroll
        for (int k = 0; k < 9; k++) {
            aSr[k] = add2(aSr[k], __shfl_xor_sync(~0u, aSr[k], o));
            aSi[k] = add2(aSi[k], __shfl_xor_sync(~0u, aSi[k], o));
            aNr[k] = add2(aNr[k], __shfl_xor_sync(~0u, aNr[k], o));
            aNi[k] = add2(aNi[k], __shfl_xor_sync(~0u, aNi[k], o));
        }
        dsum = add2(dsum, __shfl_xor_sync(~0u, dsum, o));
        dnum = add2(dnum, __shfl_xor_sync(~0u, dnum, o));
    }
    if (lane == 0) {
#pragma unroll
        for (int k = 0; k < 9; k++) {
            int p = 4 * k + w;
            float2 v;
            v = upk(aSr[k]); fin[2 + p]   = v.x + v.y;
            v = upk(aSi[k]); fin[38 + p]  = v.x + v.y;
            v = upk(aNr[k]); fin[74 + p]  = v.x + v.y;
            v = upk(aNi[k]); fin[110 + p] = v.x + v.y;
        }
        if (w == 0) {
            float2 v = upk(dsum); fin[0] = v.x + v.y;
            v = upk(dnum);        fin[1] = v.x + v.y;
        }
    }
    __syncthreads();

    // Build Sp (speech PSD) and Aug = [Noise + eps*I | I]
    if (tid < 64) {
        int c = tid >> 3, d = tid & 7;
        float dens = fmaxf(fin[0], PSD_EPSF);
        float denn = fmaxf(fin[1], PSD_EPSF);
        int lo = min(c, d), hi = max(c, d);
        int p  = lo * 8 - (lo * (lo - 1)) / 2 + (hi - lo);
        float sgn = (c <= d) ? 1.f : -1.f;
        float sre = fin[2 + p] / dens;
        float sim = sgn * fin[38 + p] / dens + (PSD_EPSF + EPSF);
        float nre = fin[74 + p] / denn;
        float nim = sgn * fin[110 + p] / denn + (PSD_EPSF + EPSF);
        if (c == d) nre += EPSF;
        Sp[c][d]      = make_float2(sre, sim);
        Aug[c][d]     = make_float2(nre, nim);
        Aug[c][d + 8] = make_float2((c == d) ? 1.f : 0.f, 0.f);
    }
    __syncthreads();

    // Gauss-Jordan inverse + MVDR weights (warp 0)
    if (tid < 32) {
        int i = tid;
        for (int k = 0; k < 8; k++) {
            if (i == k) {
                float2 piv = Aug[k][k];
                float invm = 1.f / (piv.x * piv.x + piv.y * piv.y);
                float pr = piv.x * invm, pi = -piv.y * invm;
#pragma unroll
                for (int j = 0; j < 16; j++) {
                    float2 v = Aug[k][j];
                    Aug[k][j] = make_float2(v.x * pr - v.y * pi, v.x * pi + v.y * pr);
                }
            }
            __syncwarp();
            if (i < 8 && i != k) {
                float2 fc = Aug[i][k];
#pragma unroll
                for (int j = 0; j < 16; j++) {
                    float2 v = Aug[k][j];
                    float2 q = Aug[i][j];
                    Aug[i][j] = make_float2(q.x - (fc.x * v.x - fc.y * v.y),
                                            q.y - (fc.x * v.y + fc.y * v.x));
                }
            }
            __syncwarp();
        }
        if (i < 8) {
            float2 inv[8];
#pragma unroll
            for (int d = 0; d < 8; d++) { inv[d] = Aug[i][8 + d]; inv[d].y += EPSF; }
            float2 trp = make_float2(0.f, 0.f), u = make_float2(0.f, 0.f);
#pragma unroll
            for (int d = 0; d < 8; d++) {
                float2 s1 = Sp[d][i];
                trp.x += inv[d].x * s1.x - inv[d].y * s1.y;
                trp.y += inv[d].x * s1.y + inv[d].y * s1.x;
                float2 s0 = Sp[d][0];
                u.x += inv[d].x * s0.x - inv[d].y * s0.y;
                u.y += inv[d].x * s0.y + inv[d].y * s0.x;
            }
#pragma unroll
            for (int o = 4; o > 0; o >>= 1) {
                trp.x += __shfl_xor_sync(0xFF, trp.x, o);
                trp.y += __shfl_xor_sync(0xFF, trp.y, o);
            }
            trp.x += EPSF;
            float idn = 1.f / (trp.x * trp.x + trp.y * trp.y);
            float wr = (u.x * trp.x + u.y * trp.y) * idn;
            float wi = (u.y * trp.x - u.x * trp.y) * idn;
            ws[i] = make_float2(wr, -wi);   // conj(weight)
        }
    }
    __syncthreads();

    // Apply weights: out[b,f,t] = sum_c conj(w)_c * cm[b,c,f,t]
    // cm tile was just read -> L2 resident; float4 vectorized.
    const float4* xr4 = (const float4*)cr + (size_t)b * Cn * FT4 + (size_t)f * T4;
    const float4* xi4 = (const float4*)ci + (size_t)b * Cn * FT4 + (size_t)f * T4;
    float4* outr = (float4*)out + (size_t)bf * T4;
    float4* outi = (float4*)out + (size_t)(Bn * Fn) * T4 + (size_t)bf * T4;
    float2 wl[8];
#pragma unroll
    for (int c = 0; c < 8; c++) wl[c] = ws[c];
    for (int i = tid; i < T4; i += 128) {
        float4 ar = make_float4(0.f, 0.f, 0.f, 0.f);
        float4 ai = make_float4(0.f, 0.f, 0.f, 0.f);
#pragma unroll
        for (int c = 0; c < 8; c++) {
            float4 xr = xr4[(size_t)c * FT4 + i];
            float4 xi = xi4[(size_t)c * FT4 + i];
            float2 wc = wl[c];
            ar.x += wc.x * xr.x - wc.y * xi.x;  ai.x += wc.x * xi.x + wc.y * xr.x;
            ar.y += wc.x * xr.y - wc.y * xi.y;  ai.y += wc.x * xi.y + wc.y * xr.y;
            ar.z += wc.x * xr.z - wc.y * xi.z;  ai.z += wc.x * xi.z + wc.y * xr.z;
            ar.w += wc.x * xr.w - wc.y * xi.w;  ai.w += wc.x * xi.w + wc.y * xr.w;
        }
        outr[i] = ar;
        outi[i] = ai;
    }
}

extern "C" void kernel_launch(void* const* d_in, const int* in_sizes, int n_in,
                              void* d_out, int out_size) {
    const float* sm = (const float*)d_in[0];
    const float* nm = (const float*)d_in[1];
    const float* cr = (const float*)d_in[2];
    const float* ci = (const float*)d_in[3];
    float* out = (float*)d_out;

    dim3 gA((T2 + 127) / 128, Bn, NSLAB);
    mask_partial_kernel<<<gA, 128>>>(sm, nm);

    dim3 gA2((T2 + 127) / 128, Bn);
    mask_recip_kernel<<<gA2, 128>>>();

    psd_weight_apply_kernel<<<BF, 128>>>(sm, nm, cr, ci, out);
}

// round 7
// speedup vs baseline: 1.7603x; 1.6143x over previous
#include <cuda_runtime.h>

#define EPSF     1e-8f
#define PSD_EPSF 1e-5f

typedef unsigned long long u64;

constexpr int Bn = 8, Cn = 8, Fn = 257, Tn = 1500;
constexpr int T2  = Tn / 2;          // 750 float2 per (b,f) row
constexpr int T4  = Tn / 4;          // 375 float4 per (b,f) row
constexpr int FT2 = Fn * T2;
constexpr int FT4 = Fn * T4;
constexpr int BF  = Bn * Fn;         // 2056
constexpr int NSLAB = 16;            // F split for the mask-max kernel
constexpr int FSLAB = 17;            // ceil(257/16)
constexpr int TC = 96;               // t-pairs per stage in PSD kernel
constexpr int NSTAGE = (T2 + TC - 1) / TC;   // 8 (last stage 78)

// Scratch (no allocations allowed)
__device__ float2 g_part_s[NSLAB * Bn * T2];
__device__ float2 g_part_n[NSLAB * Bn * T2];
__device__ float2 g_recip_s[Bn * T2];
__device__ float2 g_recip_n[Bn * T2];

// ---------------- packed f32x2 helpers ----------------
__device__ __forceinline__ u64 fma2(u64 a, u64 b, u64 c) {
    u64 d; asm("fma.rn.f32x2 %0,%1,%2,%3;" : "=l"(d) : "l"(a), "l"(b), "l"(c)); return d;
}
__device__ __forceinline__ u64 mul2(u64 a, u64 b) {
    u64 d; asm("mul.rn.f32x2 %0,%1,%2;" : "=l"(d) : "l"(a), "l"(b)); return d;
}
__device__ __forceinline__ u64 add2(u64 a, u64 b) {
    u64 d; asm("add.rn.f32x2 %0,%1,%2;" : "=l"(d) : "l"(a), "l"(b)); return d;
}
__device__ __forceinline__ u64 neg2(u64 a) { return a ^ 0x8000000080000000ull; }
__device__ __forceinline__ float2 upk(u64 v) {
    float2 f; f.x = __uint_as_float((unsigned)v); f.y = __uint_as_float((unsigned)(v >> 32)); return f;
}
__device__ __forceinline__ float upks(u64 v) { float2 f = upk(v); return f.x + f.y; }
__device__ __forceinline__ u64 lds64(const float2* p) {
    return *reinterpret_cast<const u64*>(p);
}

// ---------------- cp.async helpers ----------------
__device__ __forceinline__ void cpa16(void* dst_smem, const void* src) {
    unsigned d = (unsigned)__cvta_generic_to_shared(dst_smem);
    asm volatile("cp.async.cg.shared.global [%0], [%1], 16;\n" :: "r"(d), "l"(src));
}
__device__ __forceinline__ void cpa_commit() { asm volatile("cp.async.commit_group;\n"); }
template<int N> __device__ __forceinline__ void cpa_wait() {
    asm volatile("cp.async.wait_group %0;\n" :: "n"(N));
}

// ---------------------------------------------------------------------------
// A1: partial max over an F-slab per (b, t).  grid (6, Bn, NSLAB) x 128.
// ---------------------------------------------------------------------------
__global__ void mask_partial_kernel(const float* __restrict__ sm,
                                    const float* __restrict__ nm) {
    int b = blockIdx.y, z = blockIdx.z;
    int idx = blockIdx.x * 128 + threadIdx.x;
    if (idx >= T2) return;
    int f0 = z * FSLAB, f1 = min(Fn, f0 + FSLAB);
    const float2* s = (const float2*)sm + (size_t)b * FT2 + (size_t)f0 * T2 + idx;
    const float2* n = (const float2*)nm + (size_t)b * FT2 + (size_t)f0 * T2 + idx;
    float2 ms = make_float2(0.f, 0.f), mn = make_float2(0.f, 0.f);
#pragma unroll 4
    for (int f = f0; f < f1; f++) {
        float2 v = *s; s += T2;
        ms.x = fmaxf(ms.x, fabsf(v.x)); ms.y = fmaxf(ms.y, fabsf(v.y));
        float2 w = *n; n += T2;
        mn.x = fmaxf(mn.x, fabsf(w.x)); mn.y = fmaxf(mn.y, fabsf(w.y));
    }
    g_part_s[(z * Bn + b) * T2 + idx] = ms;
    g_part_n[(z * Bn + b) * T2 + idx] = mn;
}

// ---------------------------------------------------------------------------
// A2: reduce slabs, store 1/(max+eps).  grid (6, Bn) x 128.
// ---------------------------------------------------------------------------
__global__ void mask_recip_kernel() {
    int b = blockIdx.y;
    int idx = blockIdx.x * 128 + threadIdx.x;
    if (idx >= T2) return;
    float2 ms = make_float2(0.f, 0.f), mn = make_float2(0.f, 0.f);
#pragma unroll
    for (int z = 0; z < NSLAB; z++) {
        float2 v = g_part_s[(z * Bn + b) * T2 + idx];
        ms.x = fmaxf(ms.x, v.x); ms.y = fmaxf(ms.y, v.y);
        float2 w = g_part_n[(z * Bn + b) * T2 + idx];
        mn.x = fmaxf(mn.x, w.x); mn.y = fmaxf(mn.y, w.y);
    }
    g_recip_s[b * T2 + idx] = make_float2(1.f / (ms.x + EPSF), 1.f / (ms.y + EPSF));
    g_recip_n[b * T2 + idx] = make_float2(1.f / (mn.x + EPSF), 1.f / (mn.y + EPSF));
}

// ---------------------------------------------------------------------------
// Per-warp pair assignment (7 off-diagonal + 2 diagonal pairs per warp).
// ---------------------------------------------------------------------------
__device__ __constant__ unsigned char OFFC[4][7] = {
    {0,0,1,2,2,3,4}, {0,0,1,2,3,4,5}, {0,0,1,2,3,4,5}, {0,1,1,1,2,3,6}};
__device__ __constant__ unsigned char OFFD[4][7] = {
    {1,5,4,3,7,7,7}, {2,6,5,4,4,5,6}, {3,7,6,5,5,6,7}, {4,2,3,7,6,6,7}};

#define OFFP(K, C, D) { \
    u64 ar = vr[C], ai = vi[C], br = vr[D], bi = vi[D]; \
    u64 ore = fma2(ai, bi, mul2(ar, br)); \
    u64 oim = fma2(ai, br, neg2(mul2(ar, bi))); \
    oSr[K] = fma2(ms, ore, oSr[K]);  oSi[K] = fma2(ms, oim, oSi[K]); \
    oNr[K] = fma2(mn, ore, oNr[K]);  oNi[K] = fma2(mn, oim, oNi[K]); }

#define DIAGP(K, C) { \
    u64 ar = vr[C], ai = vi[C]; \
    u64 ore = fma2(ai, ai, mul2(ar, ar)); \
    dSr[K] = fma2(ms, ore, dSr[K]);  dNr[K] = fma2(mn, ore, dNr[K]); }

template<int W>
__device__ __forceinline__ void warp_stage(
    int lane, int cnt,
    const float2 (*sX)[TC], const float2 (*sM)[TC],
    u64* oSr, u64* oSi, u64* oNr, u64* oNi, u64* dSr, u64* dNr,
    u64& dsum, u64& dnum)
{
    for (int j = lane; j < cnt; j += 32) {
        u64 vr[8], vi[8];
#pragma unroll
        for (int c = 0; c < 8; c++) { vr[c] = lds64(&sX[c][j]); vi[c] = lds64(&sX[8 + c][j]); }
        u64 ms = mul2(lds64(&sM[0][j]), lds64(&sM[2][j]));
        u64 mn = mul2(lds64(&sM[1][j]), lds64(&sM[3][j]));
        if (W == 0) { dsum = add2(dsum, ms); dnum = add2(dnum, mn); }
        if (W == 0) { OFFP(0,0,1) OFFP(1,0,5) OFFP(2,1,4) OFFP(3,2,3) OFFP(4,2,7) OFFP(5,3,7) OFFP(6,4,7) DIAGP(0,0) DIAGP(1,1) }
        if (W == 1) { OFFP(0,0,2) OFFP(1,0,6) OFFP(2,1,5) OFFP(3,2,4) OFFP(4,3,4) OFFP(5,4,5) OFFP(6,5,6) DIAGP(0,2) DIAGP(1,3) }
        if (W == 2) { OFFP(0,0,3) OFFP(1,0,7) OFFP(2,1,6) OFFP(3,2,5) OFFP(4,3,5) OFFP(5,4,6) OFFP(6,5,7) DIAGP(0,4) DIAGP(1,5) }
        if (W == 3) { OFFP(0,0,4) OFFP(1,1,2) OFFP(2,1,3) OFFP(3,1,7) OFFP(4,2,6) OFFP(5,3,6) OFFP(6,6,7) DIAGP(0,6) DIAGP(1,7) }
    }
}

// ---------------------------------------------------------------------------
// Fused kernel: per (b,f) block — cp.async double-buffered PSD accumulation,
// 8x8 complex inverse, MVDR weights, and weight application.
// ---------------------------------------------------------------------------
__global__ __launch_bounds__(128, 4)
void psd_weight_apply_kernel(const float* __restrict__ smk,
                             const float* __restrict__ nmk,
                             const float* __restrict__ cr,
                             const float* __restrict__ ci,
                             float* __restrict__ out) {
    int bf = blockIdx.x;
    int b  = bf / Fn, f = bf % Fn;
    int tid = threadIdx.x, lane = tid & 31, w = tid >> 5;

    const float2* smr = (const float2*)smk + (size_t)bf * T2;
    const float2* nmr = (const float2*)nmk + (size_t)bf * T2;
    const float2* rs  = g_recip_s + b * T2;
    const float2* rn  = g_recip_n + b * T2;
    const float2* xr0 = (const float2*)cr + (size_t)b * Cn * FT2 + (size_t)f * T2;
    const float2* xi0 = (const float2*)ci + (size_t)b * Cn * FT2 + (size_t)f * T2;

    // Double-buffered staging. sX rows 0-7: real channels, 8-15: imag channels.
    // sM rows: 0=speech mask, 1=noise mask, 2=speech recip, 3=noise recip.
    __shared__ float2 sX[2][16][TC];
    __shared__ float2 sM[2][4][TC];
    __shared__ float  fin[146];
    __shared__ float2 Aug[8][16];
    __shared__ float2 Sp[8][8];
    __shared__ float2 wsh[8];

    // Issue one stage's cp.async copies (20 rows x up to 48 16B chunks).
    auto issue_stage = [&](int buf, int t0, int cnt) {
        int chunks = cnt >> 1;
        for (int i = tid; i < 20 * 48; i += 128) {
            int row = i / 48, ch = i - row * 48;
            if (ch < chunks) {
                const float2* src;
                void* dst;
                if (row < 8)       { src = xr0 + (size_t)row * FT2 + t0 + ch * 2;       dst = &sX[buf][row][ch * 2]; }
                else if (row < 16) { src = xi0 + (size_t)(row - 8) * FT2 + t0 + ch * 2; dst = &sX[buf][row][ch * 2]; }
                else if (row == 16){ src = smr + t0 + ch * 2;                            dst = &sM[buf][0][ch * 2]; }
                else if (row == 17){ src = nmr + t0 + ch * 2;                            dst = &sM[buf][1][ch * 2]; }
                else if (row == 18){ src = rs  + t0 + ch * 2;                            dst = &sM[buf][2][ch * 2]; }
                else               { src = rn  + t0 + ch * 2;                            dst = &sM[buf][3][ch * 2]; }
                cpa16(dst, src);
            }
        }
    };

    u64 oSr[7], oSi[7], oNr[7], oNi[7], dSr[2], dNr[2];
#pragma unroll
    for (int k = 0; k < 7; k++) { oSr[k] = 0; oSi[k] = 0; oNr[k] = 0; oNi[k] = 0; }
    dSr[0] = dSr[1] = dNr[0] = dNr[1] = 0;
    u64 dsum = 0, dnum = 0;

    issue_stage(0, 0, TC);
    cpa_commit();

    for (int st = 0; st < NSTAGE; st++) {
        int buf = st & 1;
        int cnt = min(TC, T2 - st * TC);
        if (st + 1 < NSTAGE) {
            int t0n = (st + 1) * TC;
            issue_stage(buf ^ 1, t0n, min(TC, T2 - t0n));
            cpa_commit();
            cpa_wait<1>();
        } else {
            cpa_wait<0>();
        }
        __syncthreads();
        if      (w == 0) warp_stage<0>(lane, cnt, sX[buf], sM[buf], oSr, oSi, oNr, oNi, dSr, dNr, dsum, dnum);
        else if (w == 1) warp_stage<1>(lane, cnt, sX[buf], sM[buf], oSr, oSi, oNr, oNi, dSr, dNr, dsum, dnum);
        else if (w == 2) warp_stage<2>(lane, cnt, sX[buf], sM[buf], oSr, oSi, oNr, oNi, dSr, dNr, dsum, dnum);
        else             warp_stage<3>(lane, cnt, sX[buf], sM[buf], oSr, oSi, oNr, oNi, dSr, dNr, dsum, dnum);
        __syncthreads();
    }

    // Unpack to f32 first (halves shuffle count), then warp tree-reduce.
    float red[32];
#pragma unroll
    for (int k = 0; k < 7; k++) {
        red[k]      = upks(oSr[k]);
        red[7 + k]  = upks(oSi[k]);
        red[14 + k] = upks(oNr[k]);
        red[21 + k] = upks(oNi[k]);
    }
    red[28] = upks(dSr[0]); red[29] = upks(dSr[1]);
    red[30] = upks(dNr[0]); red[31] = upks(dNr[1]);
    float rds = upks(dsum), rdn = upks(dnum);
#pragma unroll
    for (int o = 16; o > 0; o >>= 1) {
#pragma unroll
        for (int k = 0; k < 32; k++) red[k] += __shfl_xor_sync(~0u, red[k], o);
        if (w == 0) {
            rds += __shfl_xor_sync(~0u, rds, o);
            rdn += __shfl_xor_sync(~0u, rdn, o);
        }
    }
    if (lane == 0) {
#pragma unroll
        for (int k = 0; k < 7; k++) {
            int c = OFFC[w][k], d = OFFD[w][k];
            int p = c * 8 - (c * (c - 1)) / 2 + (d - c);
            fin[2 + p]   = red[k];
            fin[38 + p]  = red[7 + k];
            fin[74 + p]  = red[14 + k];
            fin[110 + p] = red[21 + k];
        }
#pragma unroll
        for (int k = 0; k < 2; k++) {
            int c = 2 * w + k;
            int p = c * 8 - (c * (c - 1)) / 2;
            fin[2 + p]   = red[28 + k];
            fin[38 + p]  = 0.f;
            fin[74 + p]  = red[30 + k];
            fin[110 + p] = 0.f;
        }
        if (w == 0) { fin[0] = rds; fin[1] = rdn; }
    }
    __syncthreads();

    // Build Sp (speech PSD) and Aug = [Noise + eps*I | I]
    if (tid < 64) {
        int c = tid >> 3, d = tid & 7;
        float dens = fmaxf(fin[0], PSD_EPSF);
        float denn = fmaxf(fin[1], PSD_EPSF);
        int lo = min(c, d), hi = max(c, d);
        int p  = lo * 8 - (lo * (lo - 1)) / 2 + (hi - lo);
        float sgn = (c <= d) ? 1.f : -1.f;
        float sre = fin[2 + p] / dens;
        float sim = sgn * fin[38 + p] / dens + (PSD_EPSF + EPSF);
        float nre = fin[74 + p] / denn;
        float nim = sgn * fin[110 + p] / denn + (PSD_EPSF + EPSF);
        if (c == d) nre += EPSF;
        Sp[c][d]      = make_float2(sre, sim);
        Aug[c][d]     = make_float2(nre, nim);
        Aug[c][d + 8] = make_float2((c == d) ? 1.f : 0.f, 0.f);
    }
    __syncthreads();

    // Gauss-Jordan inverse + MVDR weights (warp 0)
    if (tid < 32) {
        int i = tid;
        for (int k = 0; k < 8; k++) {
            if (i == k) {
                float2 piv = Aug[k][k];
                float invm = 1.f / (piv.x * piv.x + piv.y * piv.y);
                float pr = piv.x * invm, pi = -piv.y * invm;
#pragma unroll
                for (int j = 0; j < 16; j++) {
                    float2 v = Aug[k][j];
                    Aug[k][j] = make_float2(v.x * pr - v.y * pi, v.x * pi + v.y * pr);
                }
            }
            __syncwarp();
            if (i < 8 && i != k) {
                float2 fc = Aug[i][k];
#pragma unroll
                for (int j = 0; j < 16; j++) {
                    float2 v = Aug[k][j];
                    float2 q = Aug[i][j];
                    Aug[i][j] = make_float2(q.x - (fc.x * v.x - fc.y * v.y),
                                            q.y - (fc.x * v.y + fc.y * v.x));
                }
            }
            __syncwarp();
        }
        if (i < 8) {
            float2 inv[8];
#pragma unroll
            for (int d = 0; d < 8; d++) { inv[d] = Aug[i][8 + d]; inv[d].y += EPSF; }
            float2 trp = make_float2(0.f, 0.f), u = make_float2(0.f, 0.f);
#pragma unroll
            for (int d = 0; d < 8; d++) {
                float2 s1 = Sp[d][i];
                trp.x += inv[d].x * s1.x - inv[d].y * s1.y;
                trp.y += inv[d].x * s1.y + inv[d].y * s1.x;
                float2 s0 = Sp[d][0];
                u.x += inv[d].x * s0.x - inv[d].y * s0.y;
                u.y += inv[d].x * s0.y + inv[d].y * s0.x;
            }
#pragma unroll
            for (int o = 4; o > 0; o >>= 1) {
                trp.x += __shfl_xor_sync(0xFF, trp.x, o);
                trp.y += __shfl_xor_sync(0xFF, trp.y, o);
            }
            trp.x += EPSF;
            float idn = 1.f / (trp.x * trp.x + trp.y * trp.y);
            float wr = (u.x * trp.x + u.y * trp.y) * idn;
            float wi = (u.y * trp.x - u.x * trp.y) * idn;
            wsh[i] = make_float2(wr, -wi);   // conj(weight)
        }
    }
    __syncthreads();

    // Apply weights: out[b,f,t] = sum_c conj(w)_c * cm[b,c,f,t].
    // cm tile just read by this block -> L2 resident; float4 vectorized.
    const float4* xr4 = (const float4*)cr + (size_t)b * Cn * FT4 + (size_t)f * T4;
    const float4* xi4 = (const float4*)ci + (size_t)b * Cn * FT4 + (size_t)f * T4;
    float4* outr = (float4*)out + (size_t)bf * T4;
    float4* outi = (float4*)out + (size_t)BF * T4 + (size_t)bf * T4;
    float2 wl[8];
#pragma unroll
    for (int c = 0; c < 8; c++) wl[c] = wsh[c];
    for (int i = tid; i < T4; i += 128) {
        float4 ar = make_float4(0.f, 0.f, 0.f, 0.f);
        float4 ai = make_float4(0.f, 0.f, 0.f, 0.f);
#pragma unroll
        for (int c = 0; c < 8; c++) {
            float4 xr = xr4[(size_t)c * FT4 + i];
            float4 xi = xi4[(size_t)c * FT4 + i];
            float2 wc = wl[c];
            ar.x += wc.x * xr.x - wc.y * xi.x;  ai.x += wc.x * xi.x + wc.y * xr.x;
            ar.y += wc.x * xr.y - wc.y * xi.y;  ai.y += wc.x * xi.y + wc.y * xr.y;
            ar.z += wc.x * xr.z - wc.y * xi.z;  ai.z += wc.x * xi.z + wc.y * xr.z;
            ar.w += wc.x * xr.w - wc.y * xi.w;  ai.w += wc.x * xi.w + wc.y * xr.w;
        }
        outr[i] = ar;
        outi[i] = ai;
    }
}

extern "C" void kernel_launch(void* const* d_in, const int* in_sizes, int n_in,
                              void* d_out, int out_size) {
    const float* sm = (const float*)d_in[0];
    const float* nm = (const float*)d_in[1];
    const float* cr = (const float*)d_in[2];
    const float* ci = (const float*)d_in[3];
    float* out = (float*)d_out;

    dim3 gA((T2 + 127) / 128, Bn, NSLAB);
    mask_partial_kernel<<<gA, 128>>>(sm, nm);

    dim3 gA2((T2 + 127) / 128, Bn);
    mask_recip_kernel<<<gA2, 128>>>();

    psd_weight_apply_kernel<<<BF, 128>>>(sm, nm, cr, ci, out);
}